// round 1
// baseline (speedup 1.0000x reference)
#include <cuda_runtime.h>

#define B_TOK 8192
#define L_DIM 1024
#define D_DIM 2048
#define NE 8

#define BM 128
#define BN 128
#define BK 16

// Scratch (allocation-free rule: __device__ globals)
__device__ int g_expert[B_TOK];
__device__ int g_rank[B_TOK];
__device__ int g_counts[NE];
__device__ int g_offsets[NE + 1];
__device__ int g_sorted[B_TOK];

__global__ void init_kernel() {
    if (threadIdx.x < NE) g_counts[threadIdx.x] = 0;
}

// One warp per token: 8 gate logits, argmax, rank within expert.
__global__ void gate_kernel(const float* __restrict__ x, const float* __restrict__ y,
                            const float* __restrict__ gW, const float* __restrict__ gb) {
    int warp = (blockIdx.x * blockDim.x + threadIdx.x) >> 5;
    int lane = threadIdx.x & 31;
    if (warp >= B_TOK) return;
    const float* xr = x + (size_t)warp * L_DIM;
    const float* yr = y + (size_t)warp * L_DIM;
    float acc[NE];
#pragma unroll
    for (int e = 0; e < NE; e++) acc[e] = 0.f;
    for (int k = lane; k < D_DIM; k += 32) {
        float v = (k < L_DIM) ? xr[k] : yr[k - L_DIM];
#pragma unroll
        for (int e = 0; e < NE; e++)
            acc[e] += v * gW[e * D_DIM + k];
    }
#pragma unroll
    for (int e = 0; e < NE; e++) {
#pragma unroll
        for (int off = 16; off > 0; off >>= 1)
            acc[e] += __shfl_xor_sync(0xffffffffu, acc[e], off);
    }
    if (lane == 0) {
        int best = 0;
        float bv = acc[0] + gb[0];
#pragma unroll
        for (int e = 1; e < NE; e++) {
            float v = acc[e] + gb[e];
            if (v > bv) { bv = v; best = e; }  // strict > keeps lowest index on tie (matches top_k)
        }
        g_expert[warp] = best;
        g_rank[warp] = atomicAdd(&g_counts[best], 1);
    }
}

__global__ void scan_kernel() {
    if (threadIdx.x == 0) {
        int s = 0;
#pragma unroll
        for (int e = 0; e < NE; e++) { g_offsets[e] = s; s += g_counts[e]; }
        g_offsets[NE] = s;
    }
}

__global__ void scatter_kernel() {
    int b = blockIdx.x * blockDim.x + threadIdx.x;
    if (b < B_TOK) g_sorted[g_offsets[g_expert[b]] + g_rank[b]] = b;
}

// Grouped SGEMM: out[tok] = We[e] @ inp[tok] + be[e], tokens grouped by expert.
// A (gathered inp rows) and W are both K-contiguous -> NT-style tiling.
__global__ __launch_bounds__(256, 2)
void moe_gemm_kernel(const float* __restrict__ x, const float* __restrict__ y,
                     const float* __restrict__ We, const float* __restrict__ be,
                     float* __restrict__ out) {
    int e = blockIdx.z;
    int cnt = g_counts[e];
    int m0 = blockIdx.y * BM;
    if (m0 >= cnt) return;
    int n0 = blockIdx.x * BN;
    const int* toks = g_sorted + g_offsets[e];
    const float* W = We + (size_t)e * D_DIM * D_DIM;

    __shared__ float As[BK][BM + 4];
    __shared__ float Bs[BK][BN + 4];

    int tid = threadIdx.x;
    int tx = tid & 15;   // n direction
    int ty = tid >> 4;   // m direction

    // Tile is 128 rows x 16 cols = 512 float4; 256 threads load 2 float4 each.
    int ar0 = tid >> 2;            // 0..63
    int ar1 = ar0 + 64;            // 64..127
    int ac  = (tid & 3) << 2;      // 0,4,8,12

    int gm0 = m0 + ar0, gm1 = m0 + ar1;
    int t0 = (gm0 < cnt) ? toks[gm0] : -1;
    int t1 = (gm1 < cnt) ? toks[gm1] : -1;

    const float* wr0 = W + (size_t)(n0 + ar0) * D_DIM + ac;
    const float* wr1 = W + (size_t)(n0 + ar1) * D_DIM + ac;

    float acc[8][8];
#pragma unroll
    for (int i = 0; i < 8; i++)
#pragma unroll
        for (int j = 0; j < 8; j++) acc[i][j] = 0.f;

    for (int k0 = 0; k0 < D_DIM; k0 += BK) {
        // ---- load A tile (gathered, x/y split is uniform per k-tile) ----
        const float* src = (k0 < L_DIM) ? x : y;
        int kb = (k0 < L_DIM) ? k0 : (k0 - L_DIM);
        float4 a0 = make_float4(0.f, 0.f, 0.f, 0.f), a1 = a0;
        if (t0 >= 0) a0 = *(const float4*)(src + (size_t)t0 * L_DIM + kb + ac);
        if (t1 >= 0) a1 = *(const float4*)(src + (size_t)t1 * L_DIM + kb + ac);
        As[ac + 0][ar0] = a0.x; As[ac + 1][ar0] = a0.y;
        As[ac + 2][ar0] = a0.z; As[ac + 3][ar0] = a0.w;
        As[ac + 0][ar1] = a1.x; As[ac + 1][ar1] = a1.y;
        As[ac + 2][ar1] = a1.z; As[ac + 3][ar1] = a1.w;

        // ---- load B (weight) tile ----
        float4 b0 = *(const float4*)(wr0 + k0);
        float4 b1 = *(const float4*)(wr1 + k0);
        Bs[ac + 0][ar0] = b0.x; Bs[ac + 1][ar0] = b0.y;
        Bs[ac + 2][ar0] = b0.z; Bs[ac + 3][ar0] = b0.w;
        Bs[ac + 0][ar1] = b1.x; Bs[ac + 1][ar1] = b1.y;
        Bs[ac + 2][ar1] = b1.z; Bs[ac + 3][ar1] = b1.w;

        __syncthreads();

#pragma unroll
        for (int k = 0; k < BK; k++) {
            float a[8], b[8];
#pragma unroll
            for (int i = 0; i < 8; i++) a[i] = As[k][ty * 8 + i];
#pragma unroll
            for (int j = 0; j < 8; j++) b[j] = Bs[k][tx * 8 + j];
#pragma unroll
            for (int i = 0; i < 8; i++)
#pragma unroll
                for (int j = 0; j < 8; j++)
                    acc[i][j] += a[i] * b[j];
        }
        __syncthreads();
    }

    // ---- epilogue: add bias, scatter to original token rows ----
    const float* brow = be + (size_t)e * D_DIM + n0 + tx * 8;
    float bias[8];
#pragma unroll
    for (int j = 0; j < 8; j++) bias[j] = brow[j];

#pragma unroll
    for (int i = 0; i < 8; i++) {
        int m = m0 + ty * 8 + i;
        if (m < cnt) {
            int tok = toks[m];
            float* orow = out + (size_t)tok * D_DIM + n0 + tx * 8;
#pragma unroll
            for (int j = 0; j < 8; j++) orow[j] = acc[i][j] + bias[j];
        }
    }
}

extern "C" void kernel_launch(void* const* d_in, const int* in_sizes, int n_in,
                              void* d_out, int out_size) {
    const float* x  = (const float*)d_in[0];
    const float* y  = (const float*)d_in[1];
    const float* We = (const float*)d_in[2];
    const float* be = (const float*)d_in[3];
    const float* gW = (const float*)d_in[4];
    const float* gb = (const float*)d_in[5];
    float* out = (float*)d_out;

    init_kernel<<<1, 32>>>();
    gate_kernel<<<B_TOK / 8, 256>>>(x, y, gW, gb);
    scan_kernel<<<1, 32>>>();
    scatter_kernel<<<B_TOK / 256, 256>>>();

    dim3 grid(D_DIM / BN, (B_TOK + BM - 1) / BM, NE);  // 16 x 64 x 8, early-exit on empty m-tiles
    moe_gemm_kernel<<<grid, 256>>>(x, y, We, be, out);
}

// round 3
// speedup vs baseline: 2.4053x; 2.4053x over previous
#include <cuda_runtime.h>
#include <cstdint>

#define B_TOK 8192
#define L_DIM 1024
#define D_DIM 2048
#define NE 8

#define BM 128
#define BN 256
#define BK 32
#define NCHUNK (D_DIM / BK)          // 64
#define STAGES 3
#define STAGE_WORDS (BM * BK + BN * BK)   // 4096 + 8192 = 12288
#define STAGE_BYTES (STAGE_WORDS * 4)     // 49152
#define DYN_SMEM (STAGES * STAGE_BYTES)   // 147456

// ---------------- scratch (allocation-free rule) ----------------
__device__ int g_expert[B_TOK];
__device__ int g_rank[B_TOK];
__device__ int g_counts[NE];
__device__ int g_offsets[NE + 1];
__device__ int g_sorted[B_TOK];

__device__ __forceinline__ uint32_t smem_u32(const void* p) {
    uint32_t a;
    asm("{ .reg .u64 t; cvta.to.shared.u64 t, %1; cvt.u32.u64 %0, t; }" : "=r"(a) : "l"(p));
    return a;
}
__device__ __forceinline__ void cp16(uint32_t dst, const float* src) {
    asm volatile("cp.async.cg.shared.global [%0], [%1], 16;" :: "r"(dst), "l"(src));
}
__device__ __forceinline__ uint32_t f2tf32(float v) {
    uint32_t r;
    asm("cvt.rna.tf32.f32 %0, %1;" : "=r"(r) : "f"(v));
    return r;
}
__device__ __forceinline__ void mma_tf32(float* d, const uint32_t* a, const uint32_t* b) {
    asm volatile("mma.sync.aligned.m16n8k8.row.col.f32.tf32.tf32.f32 "
                 "{%0,%1,%2,%3}, {%4,%5,%6,%7}, {%8,%9}, {%0,%1,%2,%3};"
                 : "+f"(d[0]), "+f"(d[1]), "+f"(d[2]), "+f"(d[3])
                 : "r"(a[0]), "r"(a[1]), "r"(a[2]), "r"(a[3]), "r"(b[0]), "r"(b[1]));
}

// ---------------- gating / sort ----------------
__global__ void init_kernel() { if (threadIdx.x < NE) g_counts[threadIdx.x] = 0; }

__global__ void gate_kernel(const float* __restrict__ x, const float* __restrict__ y,
                            const float* __restrict__ gW, const float* __restrict__ gb) {
    int warp = (blockIdx.x * blockDim.x + threadIdx.x) >> 5;
    int lane = threadIdx.x & 31;
    if (warp >= B_TOK) return;
    const float* xr = x + (size_t)warp * L_DIM;
    const float* yr = y + (size_t)warp * L_DIM;
    float acc[NE];
#pragma unroll
    for (int e = 0; e < NE; e++) acc[e] = 0.f;
    for (int k = lane; k < D_DIM; k += 32) {
        float v = (k < L_DIM) ? xr[k] : yr[k - L_DIM];
#pragma unroll
        for (int e = 0; e < NE; e++) acc[e] += v * gW[e * D_DIM + k];
    }
#pragma unroll
    for (int e = 0; e < NE; e++) {
#pragma unroll
        for (int off = 16; off > 0; off >>= 1)
            acc[e] += __shfl_xor_sync(0xffffffffu, acc[e], off);
    }
    if (lane == 0) {
        int best = 0;
        float bv = acc[0] + gb[0];
#pragma unroll
        for (int e = 1; e < NE; e++) {
            float v = acc[e] + gb[e];
            if (v > bv) { bv = v; best = e; }
        }
        g_expert[warp] = best;
        g_rank[warp] = atomicAdd(&g_counts[best], 1);
    }
}

__global__ void scan_kernel() {
    if (threadIdx.x == 0) {
        int s = 0;
#pragma unroll
        for (int e = 0; e < NE; e++) { g_offsets[e] = s; s += g_counts[e]; }
        g_offsets[NE] = s;
    }
}

__global__ void scatter_kernel() {
    int b = blockIdx.x * blockDim.x + threadIdx.x;
    if (b < B_TOK) g_sorted[g_offsets[g_expert[b]] + g_rank[b]] = b;
}

// ---------------- grouped tf32 mma.sync GEMM ----------------
// Smem tile layout (per stage): A [128 rows x 32 f32] then B [256 rows x 32 f32].
// Swizzle: 16B chunk index within a 128B row: ch' = ch ^ (row & 7).
__device__ __forceinline__ void load_chunk(uint32_t sA, uint32_t sB, int ck,
                                           const float* xrow, const float* yrow,
                                           const float* wrow, int tid) {
    int row = tid >> 1, half = tid & 1;
    const float* asrc = ((ck < 32) ? xrow + ck * BK : yrow + (ck - 32) * BK) + half * 16;
    uint32_t arow = sA + (uint32_t)row * 128u;
    int rs = row & 7;
#pragma unroll
    for (int q = 0; q < 4; q++) {
        int ch = (half * 4 + q) ^ rs;
        cp16(arow + (uint32_t)ch * 16u, asrc + q * 4);
    }
    const float* bsrc = wrow + ck * BK;
    uint32_t brow = sB + (uint32_t)tid * 128u;
    int ts = tid & 7;
#pragma unroll
    for (int q = 0; q < 8; q++) {
        int ch = q ^ ts;
        cp16(brow + (uint32_t)ch * 16u, bsrc + q * 4);
    }
    asm volatile("cp.async.commit_group;");
}

__global__ __launch_bounds__(256, 1)
void moe_gemm_mma(const float* __restrict__ x, const float* __restrict__ y,
                  const float* __restrict__ We, const float* __restrict__ be,
                  float* __restrict__ out) {
    int e = blockIdx.z;
    int cnt = g_counts[e];
    int m0 = blockIdx.y * BM;
    if (m0 >= cnt) return;
    int n0 = blockIdx.x * BN;
    const int* toks = g_sorted + g_offsets[e];
    const float* W = We + (size_t)e * D_DIM * D_DIM;

    extern __shared__ float sm[];
    uint32_t sbase = smem_u32(sm);

    int tid = threadIdx.x, wid = tid >> 5, lane = tid & 31;
    int wm = wid & 1, wn = wid >> 1;          // warp tile: 64 (m) x 64 (n)
    int lrow = lane >> 2, lc = lane & 3;

    // gather pointers for A loads
    int row_a = tid >> 1;
    int ma = m0 + row_a;
    int tok_a = toks[ma < cnt ? ma : cnt - 1];
    const float* xrow = x + (size_t)tok_a * L_DIM;
    const float* yrow = y + (size_t)tok_a * L_DIM;
    const float* wrow = W + (size_t)(n0 + tid) * D_DIM;

    // fragment addressing (word indices within a stage)
    // word(r,k) = r*32 + ((k>>2) ^ (r&7))*4 + (k&3); here r&7 == lrow for all frag rows.
    int coff[8];
#pragma unroll
    for (int c = 0; c < 8; c++) coff[c] = ((c ^ lrow) << 2) + lc;
    int ab[4][2], bb[8];
#pragma unroll
    for (int i = 0; i < 4; i++) {
        ab[i][0] = (wm * 64 + i * 16 + lrow) * 32;
        ab[i][1] = ab[i][0] + 8 * 32;
    }
#pragma unroll
    for (int j = 0; j < 8; j++)
        bb[j] = BM * BK + (wn * 64 + j * 8 + lrow) * 32;

    float acc[4][8][4];
#pragma unroll
    for (int i = 0; i < 4; i++)
#pragma unroll
        for (int j = 0; j < 8; j++)
#pragma unroll
            for (int q = 0; q < 4; q++) acc[i][j][q] = 0.f;

    // prologue: prefetch 2 stages
    load_chunk(sbase, sbase + BM * BK * 4, 0, xrow, yrow, wrow, tid);
    load_chunk(sbase + STAGE_BYTES, sbase + STAGE_BYTES + BM * BK * 4, 1, xrow, yrow, wrow, tid);

    int buf = 0;
    for (int i = 0; i < NCHUNK; i++) {
        if (i == NCHUNK - 1) asm volatile("cp.async.wait_group 0;");
        else                 asm volatile("cp.async.wait_group 1;");
        __syncthreads();
        if (i + 2 < NCHUNK) {
            int nb = buf + 2; if (nb >= STAGES) nb -= STAGES;
            uint32_t st = sbase + (uint32_t)nb * STAGE_BYTES;
            load_chunk(st, st + BM * BK * 4, i + 2, xrow, yrow, wrow, tid);
        }
        const float* stage = sm + (size_t)buf * STAGE_WORDS;
#pragma unroll
        for (int step = 0; step < 4; step++) {
            int c0 = step * 2, c1 = c0 + 1;
            uint32_t a[4][4], b[8][2];
#pragma unroll
            for (int ii = 0; ii < 4; ii++) {
                a[ii][0] = f2tf32(stage[ab[ii][0] + coff[c0]]);
                a[ii][1] = f2tf32(stage[ab[ii][1] + coff[c0]]);
                a[ii][2] = f2tf32(stage[ab[ii][0] + coff[c1]]);
                a[ii][3] = f2tf32(stage[ab[ii][1] + coff[c1]]);
            }
#pragma unroll
            for (int j = 0; j < 8; j++) {
                b[j][0] = f2tf32(stage[bb[j] + coff[c0]]);
                b[j][1] = f2tf32(stage[bb[j] + coff[c1]]);
            }
#pragma unroll
            for (int ii = 0; ii < 4; ii++)
#pragma unroll
                for (int j = 0; j < 8; j++)
                    mma_tf32(acc[ii][j], a[ii], b[j]);
        }
        __syncthreads();
        buf++; if (buf >= STAGES) buf = 0;
    }

    // ---- epilogue: scatter with bias ----
    const float* brow_g = be + (size_t)e * D_DIM + n0 + wn * 64 + lc * 2;
    float2 bias[8];
#pragma unroll
    for (int j = 0; j < 8; j++) bias[j] = *(const float2*)(brow_g + j * 8);

#pragma unroll
    for (int ii = 0; ii < 4; ii++) {
#pragma unroll
        for (int h = 0; h < 2; h++) {
            int m = m0 + wm * 64 + ii * 16 + h * 8 + lrow;
            if (m < cnt) {
                int tok = toks[m];
                float* orow = out + (size_t)tok * D_DIM + n0 + wn * 64 + lc * 2;
#pragma unroll
                for (int j = 0; j < 8; j++) {
                    float2 v;
                    v.x = acc[ii][j][h * 2 + 0] + bias[j].x;
                    v.y = acc[ii][j][h * 2 + 1] + bias[j].y;
                    *(float2*)(orow + j * 8) = v;
                }
            }
        }
    }
}

extern "C" void kernel_launch(void* const* d_in, const int* in_sizes, int n_in,
                              void* d_out, int out_size) {
    const float* x  = (const float*)d_in[0];
    const float* y  = (const float*)d_in[1];
    const float* We = (const float*)d_in[2];
    const float* be = (const float*)d_in[3];
    const float* gW = (const float*)d_in[4];
    const float* gb = (const float*)d_in[5];
    float* out = (float*)d_out;

    static bool attr_set = false;
    if (!attr_set) {
        cudaFuncSetAttribute(moe_gemm_mma, cudaFuncAttributeMaxDynamicSharedMemorySize, DYN_SMEM);
        attr_set = true;
    }

    init_kernel<<<1, 32>>>();
    gate_kernel<<<B_TOK / 8, 256>>>(x, y, gW, gb);
    scan_kernel<<<1, 32>>>();
    scatter_kernel<<<B_TOK / 256, 256>>>();

    dim3 grid(D_DIM / BN, (B_TOK + BM - 1) / BM, NE);  // 8 x 64 x 8; empty m-tiles exit early
    moe_gemm_mma<<<grid, 256, DYN_SMEM>>>(x, y, We, be, out);
}

// round 4
// speedup vs baseline: 4.3762x; 1.8194x over previous
#include <cuda_runtime.h>
#include <cuda_fp16.h>
#include <cstdint>

#define B_TOK 8192
#define L_DIM 1024
#define D_DIM 2048
#define NE 8

#define BM 128
#define BN 256
#define BKH 64                       // fp16 k per chunk
#define NCH (D_DIM / BKH)            // 32
#define STAGES 3
#define A_BYTES (BM * BKH * 2)       // 16384
#define B_BYTES (BN * BKH * 2)       // 32768
#define STG_BYTES (A_BYTES + B_BYTES) // 49152
#define DYN_SMEM (STAGES * STG_BYTES) // 147456

// ---------------- scratch (allocation-free rule: __device__ globals) ----------------
__device__ int g_expert[B_TOK];
__device__ int g_rank[B_TOK];
__device__ int g_counts[NE];
__device__ int g_offsets[NE + 1];
__device__ int g_sorted[B_TOK];
__device__ __half We_h[(size_t)NE * D_DIM * D_DIM];   // 64 MB
__device__ __half inp_h[(size_t)B_TOK * D_DIM];       // 32 MB

// ---------------- helpers ----------------
__device__ __forceinline__ uint32_t smem_u32(const void* p) {
    uint32_t a;
    asm("{ .reg .u64 t; cvta.to.shared.u64 t, %1; cvt.u32.u64 %0, t; }" : "=r"(a) : "l"(p));
    return a;
}
__device__ __forceinline__ void cp16(uint32_t dst, const void* src) {
    asm volatile("cp.async.cg.shared.global [%0], [%1], 16;" :: "r"(dst), "l"(src));
}
__device__ __forceinline__ void ldsm4(uint32_t* r, uint32_t addr) {
    asm volatile("ldmatrix.sync.aligned.m8n8.x4.shared.b16 {%0,%1,%2,%3}, [%4];"
                 : "=r"(r[0]), "=r"(r[1]), "=r"(r[2]), "=r"(r[3]) : "r"(addr));
}
__device__ __forceinline__ void mma_f16(float* d, const uint32_t* a, const uint32_t* b) {
    asm volatile("mma.sync.aligned.m16n8k16.row.col.f32.f16.f16.f32 "
                 "{%0,%1,%2,%3}, {%4,%5,%6,%7}, {%8,%9}, {%0,%1,%2,%3};"
                 : "+f"(d[0]), "+f"(d[1]), "+f"(d[2]), "+f"(d[3])
                 : "r"(a[0]), "r"(a[1]), "r"(a[2]), "r"(a[3]), "r"(b[0]), "r"(b[1]));
}

// ---------------- fp16 conversion passes ----------------
__global__ void conv_we(const float* __restrict__ We) {
    size_t i = ((size_t)blockIdx.x * blockDim.x + threadIdx.x) * 8;
    float4 v0 = *(const float4*)(We + i);
    float4 v1 = *(const float4*)(We + i + 4);
    __half2 h[4];
    h[0] = __floats2half2_rn(v0.x, v0.y);
    h[1] = __floats2half2_rn(v0.z, v0.w);
    h[2] = __floats2half2_rn(v1.x, v1.y);
    h[3] = __floats2half2_rn(v1.z, v1.w);
    *(uint4*)(We_h + i) = *(uint4*)h;
}

__global__ void conv_inp(const float* __restrict__ x, const float* __restrict__ y) {
    size_t i = ((size_t)blockIdx.x * blockDim.x + threadIdx.x) * 8;
    int b = (int)(i >> 11);           // / D_DIM
    int c = (int)(i & 2047);          // % D_DIM
    const float* src = (c < L_DIM) ? (x + (size_t)b * L_DIM + c)
                                   : (y + (size_t)b * L_DIM + (c - L_DIM));
    float4 v0 = *(const float4*)src;
    float4 v1 = *(const float4*)(src + 4);
    __half2 h[4];
    h[0] = __floats2half2_rn(v0.x, v0.y);
    h[1] = __floats2half2_rn(v0.z, v0.w);
    h[2] = __floats2half2_rn(v1.x, v1.y);
    h[3] = __floats2half2_rn(v1.z, v1.w);
    *(uint4*)(inp_h + i) = *(uint4*)h;
}

// ---------------- gating / sort ----------------
__global__ void init_kernel() { if (threadIdx.x < NE) g_counts[threadIdx.x] = 0; }

__global__ void gate_kernel(const float* __restrict__ x, const float* __restrict__ y,
                            const float* __restrict__ gW, const float* __restrict__ gb) {
    int warp = (blockIdx.x * blockDim.x + threadIdx.x) >> 5;
    int lane = threadIdx.x & 31;
    if (warp >= B_TOK) return;
    const float* xr = x + (size_t)warp * L_DIM;
    const float* yr = y + (size_t)warp * L_DIM;
    float acc[NE];
#pragma unroll
    for (int e = 0; e < NE; e++) acc[e] = 0.f;
    for (int k = lane; k < D_DIM; k += 32) {
        float v = (k < L_DIM) ? xr[k] : yr[k - L_DIM];
#pragma unroll
        for (int e = 0; e < NE; e++) acc[e] += v * gW[e * D_DIM + k];
    }
#pragma unroll
    for (int e = 0; e < NE; e++) {
#pragma unroll
        for (int off = 16; off > 0; off >>= 1)
            acc[e] += __shfl_xor_sync(0xffffffffu, acc[e], off);
    }
    if (lane == 0) {
        int best = 0;
        float bv = acc[0] + gb[0];
#pragma unroll
        for (int e = 1; e < NE; e++) {
            float v = acc[e] + gb[e];
            if (v > bv) { bv = v; best = e; }
        }
        g_expert[warp] = best;
        g_rank[warp] = atomicAdd(&g_counts[best], 1);
    }
}

__global__ void scan_kernel() {
    if (threadIdx.x == 0) {
        int s = 0;
#pragma unroll
        for (int e = 0; e < NE; e++) { g_offsets[e] = s; s += g_counts[e]; }
        g_offsets[NE] = s;
    }
}

__global__ void scatter_kernel() {
    int b = blockIdx.x * blockDim.x + threadIdx.x;
    if (b < B_TOK) g_sorted[g_offsets[g_expert[b]] + g_rank[b]] = b;
}

// ---------------- grouped fp16 mma.sync GEMM ----------------
// Per-stage smem: A [128 rows x 128B] then B [256 rows x 128B].
// Swizzle: 16B chunk within 128B row: ch' = ch ^ (row & 7).
__device__ __forceinline__ void load_chunk_h(uint32_t sA, uint32_t sB, int ck,
                                             const __half* arow_p, const __half* brow_p,
                                             int tid) {
    int row = tid >> 1, half = tid & 1, rs = row & 7;
    const __half* asrc = arow_p + ck * BKH + half * 32;
    uint32_t adst = sA + (uint32_t)row * 128u;
#pragma unroll
    for (int q = 0; q < 4; q++) {
        int ch = (half * 4 + q) ^ rs;
        cp16(adst + (uint32_t)ch * 16u, asrc + q * 8);
    }
    const __half* bsrc = brow_p + ck * BKH;
    uint32_t bdst = sB + (uint32_t)tid * 128u;
    int ts = tid & 7;
#pragma unroll
    for (int q = 0; q < 8; q++)
        cp16(bdst + (uint32_t)((q ^ ts) * 16), bsrc + q * 8);
    asm volatile("cp.async.commit_group;");
}

__global__ __launch_bounds__(256, 1)
void moe_gemm_h(const float* __restrict__ be, float* __restrict__ out) {
    int e = blockIdx.z;
    int cnt = g_counts[e];
    int m0 = blockIdx.y * BM;
    if (m0 >= cnt) return;
    int n0 = blockIdx.x * BN;
    const int* toks = g_sorted + g_offsets[e];

    extern __shared__ char sm[];
    uint32_t sbase = smem_u32(sm);

    int tid = threadIdx.x, wid = tid >> 5, lane = tid & 31;
    int wm = wid & 1, wn = wid >> 1;                 // warp tile 64(m) x 64(n)
    int lrow = lane >> 2, lc = lane & 3;

    // ldmatrix addressing
    int sw = lane & 7;
    uint32_t aRowBase = (uint32_t)(wm * 64 + ((lane >> 3) & 1) * 8 + sw);
    uint32_t kpa = (uint32_t)(lane >> 4);            // 0/1
    uint32_t nRowBase = (uint32_t)(wn * 64 + (lane >> 4) * 8 + sw);
    uint32_t kpb = (uint32_t)((lane >> 3) & 1);

    // gather pointers
    int row_a = tid >> 1;
    int ma = m0 + row_a;
    int tok_a = toks[ma < cnt ? ma : cnt - 1];
    const __half* arow_p = inp_h + (size_t)tok_a * D_DIM;
    const __half* brow_p = We_h + (size_t)e * D_DIM * D_DIM + (size_t)(n0 + tid) * D_DIM;

    float acc[4][8][4];
#pragma unroll
    for (int i = 0; i < 4; i++)
#pragma unroll
        for (int j = 0; j < 8; j++)
#pragma unroll
            for (int q = 0; q < 4; q++) acc[i][j][q] = 0.f;

    load_chunk_h(sbase, sbase + A_BYTES, 0, arow_p, brow_p, tid);
    load_chunk_h(sbase + STG_BYTES, sbase + STG_BYTES + A_BYTES, 1, arow_p, brow_p, tid);

    int buf = 0;
    for (int i = 0; i < NCH; i++) {
        if (i == NCH - 1) asm volatile("cp.async.wait_group 0;");
        else              asm volatile("cp.async.wait_group 1;");
        __syncthreads();
        if (i + 2 < NCH) {
            int nb = buf + 2; if (nb >= STAGES) nb -= STAGES;
            uint32_t st = sbase + (uint32_t)nb * STG_BYTES;
            load_chunk_h(st, st + A_BYTES, i + 2, arow_p, brow_p, tid);
        }
        uint32_t sA = sbase + (uint32_t)buf * STG_BYTES;
        uint32_t sB = sA + A_BYTES;
#pragma unroll
        for (int ks = 0; ks < 4; ks++) {
            uint32_t a[4][4], b[4][4];
            uint32_t chA = (uint32_t)(((ks * 2 + kpa) ^ sw) << 4);
            uint32_t chB = (uint32_t)(((ks * 2 + kpb) ^ sw) << 4);
#pragma unroll
            for (int ii = 0; ii < 4; ii++)
                ldsm4(a[ii], sA + (aRowBase + ii * 16) * 128u + chA);
#pragma unroll
            for (int jp = 0; jp < 4; jp++)
                ldsm4(b[jp], sB + (nRowBase + jp * 16) * 128u + chB);
#pragma unroll
            for (int ii = 0; ii < 4; ii++)
#pragma unroll
                for (int jp = 0; jp < 4; jp++) {
                    mma_f16(acc[ii][jp * 2 + 0], a[ii], &b[jp][0]);
                    mma_f16(acc[ii][jp * 2 + 1], a[ii], &b[jp][2]);
                }
        }
        __syncthreads();
        buf++; if (buf >= STAGES) buf = 0;
    }

    // ---- epilogue: bias + scatter to original token rows ----
    const float* brow_g = be + (size_t)e * D_DIM + n0 + wn * 64 + lc * 2;
    float2 bias[8];
#pragma unroll
    for (int j = 0; j < 8; j++) bias[j] = *(const float2*)(brow_g + j * 8);

#pragma unroll
    for (int ii = 0; ii < 4; ii++) {
#pragma unroll
        for (int h = 0; h < 2; h++) {
            int m = m0 + wm * 64 + ii * 16 + h * 8 + lrow;
            if (m < cnt) {
                int tok = toks[m];
                float* orow = out + (size_t)tok * D_DIM + n0 + wn * 64 + lc * 2;
#pragma unroll
                for (int j = 0; j < 8; j++) {
                    float2 v;
                    v.x = acc[ii][j][h * 2 + 0] + bias[j].x;
                    v.y = acc[ii][j][h * 2 + 1] + bias[j].y;
                    *(float2*)(orow + j * 8) = v;
                }
            }
        }
    }
}

extern "C" void kernel_launch(void* const* d_in, const int* in_sizes, int n_in,
                              void* d_out, int out_size) {
    const float* x  = (const float*)d_in[0];
    const float* y  = (const float*)d_in[1];
    const float* We = (const float*)d_in[2];
    const float* be = (const float*)d_in[3];
    const float* gW = (const float*)d_in[4];
    const float* gb = (const float*)d_in[5];
    float* out = (float*)d_out;

    static bool attr_set = false;
    if (!attr_set) {
        cudaFuncSetAttribute(moe_gemm_h, cudaFuncAttributeMaxDynamicSharedMemorySize, DYN_SMEM);
        attr_set = true;
    }

    init_kernel<<<1, 32>>>();
    conv_we<<<(NE * D_DIM * D_DIM) / (256 * 8), 256>>>(We);
    conv_inp<<<(B_TOK * D_DIM) / (256 * 8), 256>>>(x, y);
    gate_kernel<<<B_TOK / 8, 256>>>(x, y, gW, gb);
    scan_kernel<<<1, 32>>>();
    scatter_kernel<<<B_TOK / 256, 256>>>();

    dim3 grid(D_DIM / BN, (B_TOK + BM - 1) / BM, NE);  // 8 x 64 x 8; empty m-tiles exit early
    moe_gemm_h<<<grid, 256, DYN_SMEM>>>(be, out);
}

// round 5
// speedup vs baseline: 5.1472x; 1.1762x over previous
#include <cuda_runtime.h>
#include <cuda_fp16.h>
#include <cstdint>

#define B_TOK 8192
#define L_DIM 1024
#define D_DIM 2048
#define NE 8

#define BM 128
#define BN 256
#define BKH 64                        // fp16 k per chunk (128B rows)
#define NCH (D_DIM / BKH)             // 32
#define STAGES 4
#define A_BYTES (BM * 128)            // 16384
#define B_BYTES (BN * 128)            // 32768
#define STG_BYTES (A_BYTES + B_BYTES) // 49152
#define DYN_SMEM (STAGES * STG_BYTES) // 196608
#define GATE_SMEM (NE * D_DIM * 4)    // 65536

#define MAX_TILES 72
#define A_TILE_HALVES (BM * D_DIM)            // 262144 halves per tile
#define A_CHUNK_HALVES (BM * BKH)             // 8192 halves = 16KB
#define B_CHUNK_HALVES (BN * BKH)             // 16384 halves = 32KB

// ---------------- scratch (allocation-free rule: __device__ globals) ----------------
__device__ int g_expert[B_TOK];
__device__ int g_rank[B_TOK];
__device__ int g_counts[NE];
__device__ int g_offsets[NE + 1];
__device__ int g_sorted[B_TOK];
__device__ int g_tilebase[NE];
__device__ int g_tile_e[MAX_TILES];
__device__ int g_tile_m0[MAX_TILES];
__device__ int g_ntiles;
__device__ __half We_h[(size_t)NE * D_DIM * D_DIM];        // 64 MB, chunk-major swizzled
__device__ __half inp_h[(size_t)MAX_TILES * A_TILE_HALVES]; // ~37.7 MB, tile/chunk-major swizzled

// ---------------- helpers ----------------
__device__ __forceinline__ uint32_t smem_u32(const void* p) {
    uint32_t a;
    asm("{ .reg .u64 t; cvta.to.shared.u64 t, %1; cvt.u32.u64 %0, t; }" : "=r"(a) : "l"(p));
    return a;
}
__device__ __forceinline__ void ldsm4(uint32_t* r, uint32_t addr) {
    asm volatile("ldmatrix.sync.aligned.m8n8.x4.shared.b16 {%0,%1,%2,%3}, [%4];"
                 : "=r"(r[0]), "=r"(r[1]), "=r"(r[2]), "=r"(r[3]) : "r"(addr));
}
__device__ __forceinline__ void mma_f16(float* d, const uint32_t* a, const uint32_t* b) {
    asm volatile("mma.sync.aligned.m16n8k16.row.col.f32.f16.f16.f32 "
                 "{%0,%1,%2,%3}, {%4,%5,%6,%7}, {%8,%9}, {%0,%1,%2,%3};"
                 : "+f"(d[0]), "+f"(d[1]), "+f"(d[2]), "+f"(d[3])
                 : "r"(a[0]), "r"(a[1]), "r"(a[2]), "r"(a[3]), "r"(b[0]), "r"(b[1]));
}
#define MBAR_INIT(addr, count) \
    asm volatile("mbarrier.init.shared.b64 [%0], %1;" :: "r"(addr), "r"((uint32_t)(count)) : "memory")
#define MBAR_EXPECT_TX(addr, bytes) \
    asm volatile("mbarrier.arrive.expect_tx.shared.b64 _, [%0], %1;" :: "r"(addr), "r"((uint32_t)(bytes)) : "memory")
#define MBAR_WAIT(addr, parity) do {                                                \
    uint32_t _m = (addr); uint32_t _p = (parity); uint32_t _done;                   \
    asm volatile("{\n\t.reg .pred p;\n\t"                                           \
        "mbarrier.try_wait.parity.acquire.cta.shared::cta.b64 p, [%1], %2;\n\t"     \
        "selp.b32 %0, 1, 0, p;\n\t}" : "=r"(_done) : "r"(_m), "r"(_p) : "memory");  \
    if (!_done) {                                                                   \
        asm volatile("{\n\t.reg .pred P1;\n\t"                                      \
            "WL_%=:\n\t"                                                            \
            "mbarrier.try_wait.parity.acquire.cta.shared::cta.b64 P1, [%0], %1, 0x989680;\n\t" \
            "@P1 bra.uni WD_%=;\n\t"                                                \
            "bra.uni WL_%=;\n\t"                                                    \
            "WD_%=:\n\t}" :: "r"(_m), "r"(_p) : "memory");                          \
    }                                                                               \
} while (0)
__device__ __forceinline__ void bulk_g2s(uint32_t dst, const void* src, uint32_t bytes, uint32_t mbar) {
    asm volatile("cp.async.bulk.shared::cluster.global.mbarrier::complete_tx::bytes [%0], [%1], %2, [%3];"
                 :: "r"(dst), "l"(src), "r"(bytes), "r"(mbar) : "memory");
}

// ---------------- gating / sort ----------------
__global__ void init_kernel() { if (threadIdx.x < NE) g_counts[threadIdx.x] = 0; }

// 32 tokens per block; gW staged in 64KB smem.
__global__ void gate_kernel(const float* __restrict__ x, const float* __restrict__ y,
                            const float* __restrict__ gW, const float* __restrict__ gb) {
    extern __shared__ float sgW[];
    int tid = threadIdx.x;
    for (int i = tid; i < NE * D_DIM / 4; i += 256)
        ((float4*)sgW)[i] = ((const float4*)gW)[i];
    __syncthreads();

    int wid = tid >> 5, lane = tid & 31;
#pragma unroll
    for (int t = 0; t < 4; t++) {
        int tok = blockIdx.x * 32 + wid * 4 + t;
        const float4* xr = (const float4*)(x + (size_t)tok * L_DIM);
        const float4* yr = (const float4*)(y + (size_t)tok * L_DIM);
        float acc[NE];
#pragma unroll
        for (int e = 0; e < NE; e++) acc[e] = 0.f;
#pragma unroll
        for (int it = 0; it < 8; it++) {
            float4 v = xr[it * 32 + lane];
            int kb = (it * 32 + lane) * 4;
#pragma unroll
            for (int e = 0; e < NE; e++) {
                float4 w = *(const float4*)(sgW + e * D_DIM + kb);
                acc[e] += v.x * w.x + v.y * w.y + v.z * w.z + v.w * w.w;
            }
        }
#pragma unroll
        for (int it = 0; it < 8; it++) {
            float4 v = yr[it * 32 + lane];
            int kb = L_DIM + (it * 32 + lane) * 4;
#pragma unroll
            for (int e = 0; e < NE; e++) {
                float4 w = *(const float4*)(sgW + e * D_DIM + kb);
                acc[e] += v.x * w.x + v.y * w.y + v.z * w.z + v.w * w.w;
            }
        }
#pragma unroll
        for (int e = 0; e < NE; e++) {
#pragma unroll
            for (int off = 16; off > 0; off >>= 1)
                acc[e] += __shfl_xor_sync(0xffffffffu, acc[e], off);
        }
        if (lane == 0) {
            int best = 0;
            float bv = acc[0] + gb[0];
#pragma unroll
            for (int e = 1; e < NE; e++) {
                float v = acc[e] + gb[e];
                if (v > bv) { bv = v; best = e; }
            }
            g_expert[tok] = best;
            g_rank[tok] = atomicAdd(&g_counts[best], 1);
        }
    }
}

__global__ void scan_kernel() {
    if (threadIdx.x == 0) {
        int s = 0, tile = 0;
#pragma unroll
        for (int e = 0; e < NE; e++) {
            g_offsets[e] = s;
            g_tilebase[e] = tile;
            int cnt = g_counts[e];
            int nt = (cnt + BM - 1) / BM;
            for (int t = 0; t < nt; t++) {
                g_tile_e[tile] = e;
                g_tile_m0[tile] = t * BM;
                tile++;
            }
            s += cnt;
        }
        g_offsets[NE] = s;
        g_ntiles = tile;
    }
}

__global__ void scatter_kernel() {
    int b = blockIdx.x * blockDim.x + threadIdx.x;
    if (b < B_TOK) g_sorted[g_offsets[g_expert[b]] + g_rank[b]] = b;
}

// ---------------- conversion to chunk-major swizzled fp16 ----------------
// We_h layout: [e][nb(8)][ck(32)][row(256)][64 halves], 16B chunk q stored at (q ^ (row&7)).
__global__ void conv_we(const float* __restrict__ We) {
    uint32_t flat = blockIdx.x * 256 + threadIdx.x;
    int q   = flat & 7;
    int row = (flat >> 3) & 255;
    int ck  = (flat >> 11) & 31;
    int nb  = (flat >> 16) & 7;
    int e   = flat >> 19;
    const float* src = We + ((((size_t)e * D_DIM) + nb * 256 + row) * D_DIM + ck * BKH + q * 8);
    float4 v0 = *(const float4*)src;
    float4 v1 = *(const float4*)(src + 4);
    __half2 h[4];
    h[0] = __floats2half2_rn(v0.x, v0.y);
    h[1] = __floats2half2_rn(v0.z, v0.w);
    h[2] = __floats2half2_rn(v1.x, v1.y);
    h[3] = __floats2half2_rn(v1.z, v1.w);
    __half* dst = We_h + (((size_t)(e * 8 + nb) * 32 + ck) * B_CHUNK_HALVES
                          + row * 64 + ((q ^ (row & 7)) << 3));
    *(uint4*)dst = *(uint4*)h;
}

// inp_h layout: [tile][ck(32)][row(128)][64 halves], swizzled; rows = sorted tokens.
__global__ void conv_inp(const float* __restrict__ x, const float* __restrict__ y) {
    int tile = blockIdx.x >> 7;
    if (tile >= g_ntiles) return;
    uint32_t fl = (blockIdx.x & 127) * 256 + threadIdx.x;   // 0..32767
    int q   = fl & 7;
    int row = (fl >> 3) & 127;
    int ck  = fl >> 10;
    int e = g_tile_e[tile];
    int m = g_tile_m0[tile] + row;
    __half2 h[4];
    if (m < g_counts[e]) {
        int tok = g_sorted[g_offsets[e] + m];
        int col = ck * BKH + q * 8;
        const float* src = (col < L_DIM) ? (x + (size_t)tok * L_DIM + col)
                                         : (y + (size_t)tok * L_DIM + (col - L_DIM));
        float4 v0 = *(const float4*)src;
        float4 v1 = *(const float4*)(src + 4);
        h[0] = __floats2half2_rn(v0.x, v0.y);
        h[1] = __floats2half2_rn(v0.z, v0.w);
        h[2] = __floats2half2_rn(v1.x, v1.y);
        h[3] = __floats2half2_rn(v1.z, v1.w);
    } else {
        h[0] = h[1] = h[2] = h[3] = __half2half2(__float2half(0.f));
    }
    __half* dst = inp_h + ((size_t)tile * A_TILE_HALVES + (size_t)ck * A_CHUNK_HALVES
                           + row * 64 + ((q ^ (row & 7)) << 3));
    *(uint4*)dst = *(uint4*)h;
}

// ---------------- grouped fp16 mma.sync GEMM with bulk-async loads ----------------
__global__ __launch_bounds__(256, 1)
void moe_gemm_h(const float* __restrict__ be, float* __restrict__ out) {
    int e = blockIdx.z;
    int cnt = g_counts[e];
    int m0 = blockIdx.y * BM;
    if (m0 >= cnt) return;
    int n0 = blockIdx.x * BN;
    const int* toks = g_sorted + g_offsets[e];
    int tile = g_tilebase[e] + blockIdx.y;

    const __half* asrc = inp_h + (size_t)tile * A_TILE_HALVES;
    const __half* bsrc = We_h + ((size_t)(e * 8 + blockIdx.x) * 32) * B_CHUNK_HALVES;

    extern __shared__ char sm[];
    uint32_t sbase = smem_u32(sm);
    __shared__ __align__(8) uint64_t s_mbar[STAGES];
    uint32_t mb[STAGES];
#pragma unroll
    for (int s = 0; s < STAGES; s++) mb[s] = smem_u32(&s_mbar[s]);

    int tid = threadIdx.x, wid = tid >> 5, lane = tid & 31;
    int wm = wid & 1, wn = wid >> 1;          // warp tile 64(m) x 64(n)
    int lrow = lane >> 2, lc = lane & 3;
    int sw = lane & 7;
    uint32_t aRowBase = (uint32_t)(wm * 64 + ((lane >> 3) & 1) * 8 + sw);
    uint32_t kpa = (uint32_t)(lane >> 4);
    uint32_t nRowBase = (uint32_t)(wn * 64 + (lane >> 4) * 8 + sw);
    uint32_t kpb = (uint32_t)((lane >> 3) & 1);

    if (tid == 0) {
#pragma unroll
        for (int s = 0; s < STAGES; s++) MBAR_INIT(mb[s], 1);
    }
    __syncthreads();

    // prologue: stages 0..2
    if (tid == 0) {
#pragma unroll
        for (int s = 0; s < STAGES - 1; s++) {
            uint32_t dst = sbase + s * STG_BYTES;
            MBAR_EXPECT_TX(mb[s], STG_BYTES);
            bulk_g2s(dst, asrc + (size_t)s * A_CHUNK_HALVES, A_BYTES, mb[s]);
            bulk_g2s(dst + A_BYTES, bsrc + (size_t)s * B_CHUNK_HALVES, B_BYTES, mb[s]);
        }
    }

    float acc[4][8][4];
#pragma unroll
    for (int i = 0; i < 4; i++)
#pragma unroll
        for (int j = 0; j < 8; j++)
#pragma unroll
            for (int q = 0; q < 4; q++) acc[i][j][q] = 0.f;

    for (int i = 0; i < NCH; i++) {
        int buf = i & (STAGES - 1);
        if (tid == 0 && i + STAGES - 1 < NCH) {
            int nb = (i + STAGES - 1) & (STAGES - 1);
            uint32_t dst = sbase + nb * STG_BYTES;
            MBAR_EXPECT_TX(mb[nb], STG_BYTES);
            bulk_g2s(dst, asrc + (size_t)(i + STAGES - 1) * A_CHUNK_HALVES, A_BYTES, mb[nb]);
            bulk_g2s(dst + A_BYTES, bsrc + (size_t)(i + STAGES - 1) * B_CHUNK_HALVES, B_BYTES, mb[nb]);
        }
        MBAR_WAIT(mb[buf], (uint32_t)((i >> 2) & 1));

        uint32_t sA = sbase + buf * STG_BYTES;
        uint32_t sB = sA + A_BYTES;
#pragma unroll
        for (int ks = 0; ks < 4; ks++) {
            uint32_t a[4][4], b[4][4];
            uint32_t chA = (uint32_t)(((ks * 2 + kpa) ^ sw) << 4);
            uint32_t chB = (uint32_t)(((ks * 2 + kpb) ^ sw) << 4);
#pragma unroll
            for (int ii = 0; ii < 4; ii++)
                ldsm4(a[ii], sA + (aRowBase + ii * 16) * 128u + chA);
#pragma unroll
            for (int jp = 0; jp < 4; jp++)
                ldsm4(b[jp], sB + (nRowBase + jp * 16) * 128u + chB);
#pragma unroll
            for (int ii = 0; ii < 4; ii++)
#pragma unroll
                for (int jp = 0; jp < 4; jp++) {
                    mma_f16(acc[ii][jp * 2 + 0], a[ii], &b[jp][0]);
                    mma_f16(acc[ii][jp * 2 + 1], a[ii], &b[jp][2]);
                }
        }
        __syncthreads();
    }

    // ---- epilogue: bias + scatter to original token rows ----
    const float* brow_g = be + (size_t)e * D_DIM + n0 + wn * 64 + lc * 2;
    float2 bias[8];
#pragma unroll
    for (int j = 0; j < 8; j++) bias[j] = *(const float2*)(brow_g + j * 8);

#pragma unroll
    for (int ii = 0; ii < 4; ii++) {
#pragma unroll
        for (int h = 0; h < 2; h++) {
            int m = m0 + wm * 64 + ii * 16 + h * 8 + lrow;
            if (m < cnt) {
                int tok = toks[m];
                float* orow = out + (size_t)tok * D_DIM + n0 + wn * 64 + lc * 2;
#pragma unroll
                for (int j = 0; j < 8; j++) {
                    float2 v;
                    v.x = acc[ii][j][h * 2 + 0] + bias[j].x;
                    v.y = acc[ii][j][h * 2 + 1] + bias[j].y;
                    *(float2*)(orow + j * 8) = v;
                }
            }
        }
    }
}

extern "C" void kernel_launch(void* const* d_in, const int* in_sizes, int n_in,
                              void* d_out, int out_size) {
    const float* x  = (const float*)d_in[0];
    const float* y  = (const float*)d_in[1];
    const float* We = (const float*)d_in[2];
    const float* be = (const float*)d_in[3];
    const float* gW = (const float*)d_in[4];
    const float* gb = (const float*)d_in[5];
    float* out = (float*)d_out;

    static bool attr_set = false;
    if (!attr_set) {
        cudaFuncSetAttribute(moe_gemm_h, cudaFuncAttributeMaxDynamicSharedMemorySize, DYN_SMEM);
        cudaFuncSetAttribute(gate_kernel, cudaFuncAttributeMaxDynamicSharedMemorySize, GATE_SMEM);
        attr_set = true;
    }

    init_kernel<<<1, 32>>>();
    gate_kernel<<<B_TOK / 32, 256, GATE_SMEM>>>(x, y, gW, gb);
    scan_kernel<<<1, 32>>>();
    scatter_kernel<<<B_TOK / 256, 256>>>();
    conv_we<<<(NE * D_DIM * D_DIM) / (256 * 8), 256>>>(We);
    conv_inp<<<MAX_TILES * 128, 256>>>(x, y);

    dim3 grid(D_DIM / BN, (B_TOK + BM - 1) / BM, NE);  // 8 x 64 x 8; empty m-tiles exit early
    moe_gemm_h<<<grid, 256, DYN_SMEM>>>(be, out);
}